// round 3
// baseline (speedup 1.0000x reference)
#include <cuda_runtime.h>
#include <cstdint>
#include <math_constants.h>

// Problem constants
#define NROWS   131072      // 256*512
#define DDIM    64
#define ECODES  1024
#define CHUNK   128         // codes staged in smem per iteration
#define NCHUNK  (ECODES / CHUNK)
#define BLOCK   256
#define RPB     256         // rows per block (1 thread = 1 row)
#define GRID    (NROWS / RPB)
#define WSTRIDE 130         // padded row stride (floats) for wsh

__device__ float g_loss_acc;
__device__ float g_t2[ECODES];

// ---- packed f32x2 helpers (Blackwell FFMA2: bitwise identical to 2x scalar IEEE fp32 FMA) ----
__device__ __forceinline__ unsigned long long f32x2_pack(float a, float b) {
    unsigned long long r;
    asm("mov.b64 %0, {%1, %2};" : "=l"(r) : "f"(a), "f"(b));
    return r;
}
__device__ __forceinline__ void f32x2_unpack(unsigned long long v, float& a, float& b) {
    asm("mov.b64 {%0, %1}, %2;" : "=f"(a), "=f"(b) : "l"(v));
}
__device__ __forceinline__ unsigned long long f32x2_fma(unsigned long long a,
                                                        unsigned long long b,
                                                        unsigned long long c) {
    unsigned long long r;
    asm("fma.rn.f32x2 %0, %1, %2, %3;" : "=l"(r) : "l"(a), "l"(b), "l"(c));
    return r;
}

// ---- prep: t2[c] = sum_k fl(w[c][k]^2) (rounded products, sequential adds), zero loss acc ----
__global__ __launch_bounds__(256) void vq_prep_kernel(const float* __restrict__ wt) {
    int c = blockIdx.x * blockDim.x + threadIdx.x;
    if (c == 0) g_loss_acc = 0.0f;
    if (c < ECODES) {
        const float* wr = wt + (size_t)c * DDIM;
        float s = 0.0f;
        #pragma unroll
        for (int k = 0; k < DDIM; k++)
            s = __fadd_rn(s, __fmul_rn(wr[k], wr[k]));
        g_t2[c] = s;
    }
}

// ---- main: distances + argmin + all outputs ----
__global__ __launch_bounds__(BLOCK) void vq_main_kernel(
    const float* __restrict__ inp,   // [131072, 64]
    const float* __restrict__ wt,    // [1024, 64]
    float* out_q,                    // [131072, 64] or null
    float* out_enc)                  // [131072, 1024] or null (may be only 4B-aligned!)
{
    __shared__ __align__(16) float wsh[DDIM * WSTRIDE];  // transposed chunk: wsh[k][c]
    __shared__ float t2sh[CHUNK];
    __shared__ int   idx_sh[RPB];
    __shared__ float red[BLOCK];

    const int tid = threadIdx.x;
    const size_t rowbase = (size_t)blockIdx.x * RPB;
    const size_t row = rowbase + tid;

    // Load this thread's row into registers
    float x[DDIM];
    {
        const float4* xin = reinterpret_cast<const float4*>(inp + row * DDIM);
        #pragma unroll
        for (int i = 0; i < DDIM / 4; i++) {
            float4 v = xin[i];
            x[4 * i + 0] = v.x; x[4 * i + 1] = v.y;
            x[4 * i + 2] = v.z; x[4 * i + 3] = v.w;
        }
    }

    // term1: rounded squares, sequential fp32 adds (replicates sum(flat*flat, axis=1))
    float t1 = 0.0f;
    #pragma unroll
    for (int k = 0; k < DDIM; k++)
        t1 = __fadd_rn(t1, __fmul_rn(x[k], x[k]));

    float best = CUDART_INF_F;
    int bidx = 0;

    for (int ch = 0; ch < NCHUNK; ch++) {
        __syncthreads();
        // Stage weight chunk transposed: wsh[k][c] = weight[ch*128 + c][k]
        {
            const float* wg = wt + (size_t)ch * CHUNK * DDIM;
            for (int i = tid; i < CHUNK * DDIM; i += BLOCK) {
                int c = i >> 6;
                int k = i & 63;
                wsh[k * WSTRIDE + c] = wg[i];
            }
            if (tid < CHUNK) t2sh[tid] = g_t2[ch * CHUNK + tid];
        }
        __syncthreads();

        for (int g = 0; g < CHUNK / 8; g++) {   // 8 codes (4 f32x2 pairs) per pass
            unsigned long long acc0 = 0ull, acc1 = 0ull, acc2 = 0ull, acc3 = 0ull;
            #pragma unroll
            for (int k = 0; k < DDIM; k++) {
                unsigned long long xk2 = f32x2_pack(x[k], x[k]);
                const unsigned long long* wrow =
                    reinterpret_cast<const unsigned long long*>(wsh + k * WSTRIDE) + g * 4;
                acc0 = f32x2_fma(xk2, wrow[0], acc0);
                acc1 = f32x2_fma(xk2, wrow[1], acc1);
                acc2 = f32x2_fma(xk2, wrow[2], acc2);
                acc3 = f32x2_fma(xk2, wrow[3], acc3);
            }
            const int cbase = ch * CHUNK + g * 8;
            unsigned long long accs[4] = {acc0, acc1, acc2, acc3};
            #pragma unroll
            for (int p = 0; p < 4; p++) {
                float d0, d1;
                f32x2_unpack(accs[p], d0, d1);
                int c0 = cbase + 2 * p;
                // dist = fl(fl(t1 + t2) - fl(2*dot)); 2*dot is exact (scale by power of 2)
                float u0 = __fadd_rn(t1, t2sh[g * 8 + 2 * p]);
                float dist0 = __fsub_rn(u0, __fmul_rn(2.0f, d0));
                if (dist0 < best) { best = dist0; bidx = c0; }
                float u1 = __fadd_rn(t1, t2sh[g * 8 + 2 * p + 1]);
                float dist1 = __fsub_rn(u1, __fmul_rn(2.0f, d1));
                if (dist1 < best) { best = dist1; bidx = c0 + 1; }
            }
        }
    }

    idx_sh[tid] = bidx;

    // Zero this block's encodings region. out_enc may be only 4-byte aligned
    // (it sits at float offset 1+8388608 in d_out), so peel to a 16B boundary,
    // vector-fill the body, scalar tail.
    if (out_enc) {
        float* ebase = out_enc + rowbase * (size_t)ECODES;
        const int total = RPB * ECODES;                       // 262144 floats
        const int head = (int)(((16u - ((uintptr_t)ebase & 15u)) & 15u) >> 2);
        if (tid < head) ebase[tid] = 0.0f;
        float4* v = reinterpret_cast<float4*>(ebase + head);  // 16B aligned
        const int nvec = (total - head) >> 2;
        float4 z = make_float4(0.f, 0.f, 0.f, 0.f);
        #pragma unroll 4
        for (int i = tid; i < nvec; i += BLOCK)
            v[i] = z;
        const int tail_start = head + (nvec << 2);
        if (tid < total - tail_start) ebase[tail_start + tid] = 0.0f;
    }
    __syncthreads();  // idx_sh visible + zeros complete before scatter of ones

    if (out_enc)
        out_enc[(rowbase + tid) * (size_t)ECODES + (size_t)bidx] = 1.0f;

    // quantized_st = fl(x + fl(q - x)); loss partial = sum fl((fl(q-x))^2)
    float part = 0.0f;
    for (int i = tid; i < RPB * DDIM; i += BLOCK) {
        int r = i >> 6;
        int k = i & 63;
        float q  = wt[(size_t)idx_sh[r] * DDIM + k];
        float xv = inp[(rowbase + r) * DDIM + k];
        float dqx = __fsub_rn(q, xv);
        part = __fadd_rn(part, __fmul_rn(dqx, dqx));
        if (out_q)
            out_q[rowbase * DDIM + i] = __fadd_rn(xv, dqx);   // scalar: 4B-aligned safe
    }

    // block reduce loss partial, one atomic per block
    red[tid] = part;
    __syncthreads();
    for (int s = BLOCK / 2; s > 0; s >>= 1) {
        if (tid < s) red[tid] += red[tid + s];
        __syncthreads();
    }
    if (tid == 0) atomicAdd(&g_loss_acc, red[0]);
}

// ---- finalize loss: loss = m + 0.25*m, m = mean((q-x)^2) ----
__global__ __launch_bounds__(32) void vq_fin_kernel(float* out_loss) {
    if (threadIdx.x == 0 && blockIdx.x == 0) {
        float m = g_loss_acc / 8388608.0f;
        out_loss[0] = __fadd_rn(m, __fmul_rn(0.25f, m));
    }
}

extern "C" void kernel_launch(void* const* d_in, const int* in_sizes, int n_in,
                              void* d_out, int out_size)
{
    const float* inp = nullptr;
    const float* wt  = nullptr;
    for (int i = 0; i < n_in; i++) {
        if (in_sizes[i] == 8388608) inp = (const float*)d_in[i];
        else if (in_sizes[i] == 65536) wt = (const float*)d_in[i];
    }
    if (!inp || !wt) return;  // unidentifiable inputs: do nothing rather than fault

    float* out = (float*)d_out;
    const long long Q = 8388608LL, ENC = 134217728LL;
    long long os = (long long)out_size;

    float* oL = nullptr; float* oQ = nullptr; float* oE = nullptr;
    if (os == 1 + Q + ENC)      { oL = out; oQ = out + 1; oE = out + 1 + Q; }
    else if (os == Q + ENC)     { oQ = out; oE = out + Q; }
    else if (os == ENC)         { oE = out; }
    else if (os == Q)           { oQ = out; }
    else if (os == 1)           { oL = out; }
    else {                       // fallback: assume (loss, quantized, encodings) prefix order
        oL = out;
        if (os >= 1 + Q) oQ = out + 1;
        if (os >= 1 + Q + ENC) oE = out + 1 + Q;
    }

    vq_prep_kernel<<<(ECODES + 255) / 256, 256>>>(wt);
    vq_main_kernel<<<GRID, BLOCK>>>(inp, wt, oQ, oE);
    if (oL) vq_fin_kernel<<<1, 32>>>(oL);
}

// round 6
// speedup vs baseline: 1.3558x; 1.3558x over previous
#include <cuda_runtime.h>
#include <cstdint>
#include <math_constants.h>

// Problem constants
#define NROWS   131072      // 256*512
#define DDIM    64
#define ECODES  1024
#define CHUNK   128         // codes per chunk
#define NCHUNK  (ECODES / CHUNK)
#define BLOCK   256
#define RPB     128         // rows per CTA
#define GRID    (NROWS / RPB)

// smem layout sizes
#define XD_STRIDE 65                    // ULL per row (64 data + 1 pad)
#define XD_ULL    (RPB * XD_STRIDE)     // 8320 ULL = 66560 B
#define W_KSTRIDE 162                   // floats per k row (16 groups * 10 + 2)
#define W_FLOATS  (DDIM * W_KSTRIDE)    // 10368 floats = 41472 B
#define SMEM_BYTES (XD_ULL*8 + W_FLOATS*4 + CHUNK*4 /*t2*/ + RPB*4 /*idx*/ + BLOCK*4 /*red*/)

typedef unsigned long long ull;

__device__ float g_loss_acc;
__device__ float g_t2[ECODES];

__device__ __forceinline__ ull f32x2_pack(float a, float b) {
    ull r; asm("mov.b64 %0, {%1, %2};" : "=l"(r) : "f"(a), "f"(b)); return r;
}
__device__ __forceinline__ void f32x2_unpack(ull v, float& a, float& b) {
    asm("mov.b64 {%0, %1}, %2;" : "=f"(a), "=f"(b) : "l"(v));
}
__device__ __forceinline__ ull f32x2_fma(ull a, ull b, ull c) {
    ull r; asm("fma.rn.f32x2 %0, %1, %2, %3;" : "=l"(r) : "l"(a), "l"(b), "l"(c)); return r;
}

// ---- prep: t2[c] = sum_k fl(w[c][k]^2), sequential adds; zero loss acc ----
__global__ __launch_bounds__(256) void vq_prep_kernel(const float* __restrict__ wt) {
    int c = blockIdx.x * blockDim.x + threadIdx.x;
    if (c == 0) g_loss_acc = 0.0f;
    if (c < ECODES) {
        const float* wr = wt + (size_t)c * DDIM;
        float s = 0.0f;
        #pragma unroll
        for (int k = 0; k < DDIM; k++)
            s = __fadd_rn(s, __fmul_rn(wr[k], wr[k]));
        g_t2[c] = s;
    }
}

// ---- main: register-blocked distances + argmin + all outputs ----
__global__ __launch_bounds__(BLOCK, 2) void vq_main_kernel(
    const float* __restrict__ inp,   // [131072, 64]
    const float* __restrict__ wt,    // [1024, 64]
    float* out_q,                    // [131072, 64] or null
    float* out_enc)                  // [131072, 1024] or null (only 4B-aligned)
{
    extern __shared__ __align__(16) char smem_raw[];
    ull*   xdup  = reinterpret_cast<ull*>(smem_raw);                    // [128][65] (x,x) pairs
    float* wsh   = reinterpret_cast<float*>(smem_raw + XD_ULL * 8);     // [64][162] grouped codes
    float* t2sh  = wsh + W_FLOATS;                                      // [128]
    int*   idx_sh= reinterpret_cast<int*>(t2sh + CHUNK);                // [128]
    float* red   = reinterpret_cast<float*>(idx_sh + RPB);              // [256]

    const int tid = threadIdx.x;
    const int rg  = tid >> 4;        // 0..15 : row group (8 rows)
    const int cg  = tid & 15;        // 0..15 : code group (8 codes per chunk)
    const size_t rowbase = (size_t)blockIdx.x * RPB;

    // ---- stage x duplicated as (x,x) pairs; coalesced gmem read ----
    {
        const float* gx = inp + rowbase * DDIM;
        for (int i = tid; i < RPB * DDIM; i += BLOCK) {
            float v = gx[i];
            xdup[(i >> 6) * XD_STRIDE + (i & 63)] = f32x2_pack(v, v);
        }
    }
    __syncthreads();

    // ---- t1 per owned row: sequential fl(x^2) adds ----
    float t1[8];
    #pragma unroll
    for (int r = 0; r < 8; r++) {
        const float* xr = reinterpret_cast<const float*>(xdup + (rg * 8 + r) * XD_STRIDE);
        float s = 0.0f;
        #pragma unroll
        for (int k = 0; k < DDIM; k++) {
            float xv = xr[2 * k];                 // low lane of (x,x)
            s = __fadd_rn(s, __fmul_rn(xv, xv));
        }
        t1[r] = s;
    }

    float best[8]; int bidx[8];
    #pragma unroll
    for (int r = 0; r < 8; r++) { best[r] = CUDART_INF_F; bidx[r] = 0; }

    for (int ch = 0; ch < NCHUNK; ch++) {
        __syncthreads();
        // stage weight chunk: code c -> wsh[k*162 + (c>>3)*10 + (c&7)]
        {
            const float* wg = wt + (size_t)ch * CHUNK * DDIM;
            for (int i = tid; i < CHUNK * DDIM; i += BLOCK) {
                int c = i >> 6, k = i & 63;
                wsh[k * W_KSTRIDE + (c >> 3) * 10 + (c & 7)] = wg[i];
            }
            if (tid < CHUNK) t2sh[tid] = g_t2[ch * CHUNK + tid];
        }
        __syncthreads();

        ull acc[8][4];
        #pragma unroll
        for (int r = 0; r < 8; r++)
            #pragma unroll
            for (int p = 0; p < 4; p++) acc[r][p] = 0ull;

        const ull* xbase = xdup + rg * 8 * XD_STRIDE;
        #pragma unroll 2
        for (int k = 0; k < DDIM; k++) {
            ull wv[4];
            const ull* wrow = reinterpret_cast<const ull*>(wsh + k * W_KSTRIDE + cg * 10);
            #pragma unroll
            for (int p = 0; p < 4; p++) wv[p] = wrow[p];
            ull xr[8];
            #pragma unroll
            for (int r = 0; r < 8; r++) xr[r] = xbase[r * XD_STRIDE + k];
            #pragma unroll
            for (int r = 0; r < 8; r++)
                #pragma unroll
                for (int p = 0; p < 4; p++)
                    acc[r][p] = f32x2_fma(xr[r], wv[p], acc[r][p]);
        }

        // epilogue: distances + running argmin, flat loop over 8 rows.
        // Within a thread codes ascend (2p, 2p+1), strict '<' => first-index ties.
        const int cbase = ch * CHUNK + cg * 8;
        #pragma unroll
        for (int r = 0; r < 8; r++) {
            float b = best[r]; int bi = bidx[r];
            #pragma unroll
            for (int p = 0; p < 4; p++) {
                float d0, d1; f32x2_unpack(acc[r][p], d0, d1);
                float u0 = __fadd_rn(t1[r], t2sh[cg * 8 + 2 * p]);
                float dist0 = __fsub_rn(u0, __fmul_rn(2.0f, d0));
                if (dist0 < b) { b = dist0; bi = cbase + 2 * p; }
                float u1 = __fadd_rn(t1[r], t2sh[cg * 8 + 2 * p + 1]);
                float dist1 = __fsub_rn(u1, __fmul_rn(2.0f, d1));
                if (dist1 < b) { b = dist1; bi = cbase + 2 * p + 1; }
            }
            best[r] = b; bidx[r] = bi;
        }
    }

    // ---- cross-thread argmin over the 16 code-groups (width-16 shuffle) ----
    #pragma unroll
    for (int r = 0; r < 8; r++) {
        float d = best[r]; int ix = bidx[r];
        #pragma unroll
        for (int off = 1; off < 16; off <<= 1) {
            float d2 = __shfl_xor_sync(0xffffffffu, d, off, 16);
            int   i2 = __shfl_xor_sync(0xffffffffu, ix, off, 16);
            if (d2 < d || (d2 == d && i2 < ix)) { d = d2; ix = i2; }
        }
        if (cg == 0) idx_sh[rg * 8 + r] = ix;
    }

    // ---- zero encodings (alignment-safe: peel to 16B, vector body, tail) ----
    if (out_enc) {
        float* ebase = out_enc + rowbase * (size_t)ECODES;
        const int total = RPB * ECODES;
        const int head = (int)(((16u - ((uintptr_t)ebase & 15u)) & 15u) >> 2);
        if (tid < head) ebase[tid] = 0.0f;
        float4* v = reinterpret_cast<float4*>(ebase + head);
        const int nvec = (total - head) >> 2;
        float4 z = make_float4(0.f, 0.f, 0.f, 0.f);
        for (int i = tid; i < nvec; i += BLOCK) v[i] = z;
        const int tail_start = head + (nvec << 2);
        if (tid < total - tail_start) ebase[tail_start + tid] = 0.0f;
    }
    __syncthreads();   // idx_sh visible + zeros done before scatter

    if (out_enc && tid < RPB)
        out_enc[(rowbase + tid) * (size_t)ECODES + (size_t)idx_sh[tid]] = 1.0f;

    // ---- quantized_st + loss partial ----
    float part = 0.0f;
    for (int i = tid; i < RPB * DDIM; i += BLOCK) {
        int r = i >> 6, k = i & 63;
        float q  = wt[(size_t)idx_sh[r] * DDIM + k];
        float xv = inp[(rowbase + r) * DDIM + k];
        float dqx = __fsub_rn(q, xv);
        part = __fadd_rn(part, __fmul_rn(dqx, dqx));
        if (out_q)
            out_q[rowbase * DDIM + i] = __fadd_rn(xv, dqx);
    }
    red[tid] = part;
    __syncthreads();
    for (int s = BLOCK / 2; s > 0; s >>= 1) {
        if (tid < s) red[tid] += red[tid + s];
        __syncthreads();
    }
    if (tid == 0) atomicAdd(&g_loss_acc, red[0]);
}

// ---- finalize loss ----
__global__ __launch_bounds__(32) void vq_fin_kernel(float* out_loss) {
    if (threadIdx.x == 0 && blockIdx.x == 0) {
        float m = g_loss_acc / 8388608.0f;
        out_loss[0] = __fadd_rn(m, __fmul_rn(0.25f, m));
    }
}

extern "C" void kernel_launch(void* const* d_in, const int* in_sizes, int n_in,
                              void* d_out, int out_size)
{
    const float* inp = nullptr;
    const float* wt  = nullptr;
    for (int i = 0; i < n_in; i++) {
        if (in_sizes[i] == 8388608) inp = (const float*)d_in[i];
        else if (in_sizes[i] == 65536) wt = (const float*)d_in[i];
    }
    if (!inp || !wt) return;

    float* out = (float*)d_out;
    const long long Q = 8388608LL, ENC = 134217728LL;
    long long os = (long long)out_size;

    float* oL = nullptr; float* oQ = nullptr; float* oE = nullptr;
    if (os == 1 + Q + ENC)      { oL = out; oQ = out + 1; oE = out + 1 + Q; }
    else if (os == Q + ENC)     { oQ = out; oE = out + Q; }
    else if (os == ENC)         { oE = out; }
    else if (os == Q)           { oQ = out; }
    else if (os == 1)           { oL = out; }
    else {
        oL = out;
        if (os >= 1 + Q) oQ = out + 1;
        if (os >= 1 + Q + ENC) oE = out + 1 + Q;
    }

    // opt-in to >48KB dynamic smem (idempotent; non-stream API, capture-safe)
    cudaFuncSetAttribute(vq_main_kernel,
                         cudaFuncAttributeMaxDynamicSharedMemorySize, SMEM_BYTES);

    vq_prep_kernel<<<(ECODES + 255) / 256, 256>>>(wt);
    vq_main_kernel<<<GRID, BLOCK, SMEM_BYTES>>>(inp, wt, oQ, oE);
    if (oL) vq_fin_kernel<<<1, 32>>>(oL);
}